// round 5
// baseline (speedup 1.0000x reference)
#include <cuda_runtime.h>
#include <cuda_fp16.h>
#include <math.h>
#include <stdint.h>

#define T_TOK 8192
#define D_DIM 1024
#define H_DIM 4096
#define E_NUM 8
#define OUT_ELEMS (T_TOK * D_DIM)

// ---------------- scratch ----------------
__device__ __half g_x16[(size_t)T_TOK * D_DIM];            // 16 MiB
__device__ __half g_w1h[(size_t)E_NUM * D_DIM * H_DIM];    // 64 MiB
__device__ __half g_w2h[(size_t)E_NUM * H_DIM * D_DIM];    // 64 MiB
__device__ __half g_mid[(size_t)2 * T_TOK * H_DIM];        // 128 MiB
__device__ int   g_cnt[E_NUM];
__device__ int   g_tok[E_NUM * T_TOK];
__device__ int   g_slot[E_NUM * T_TOK];
__device__ float g_wt[E_NUM * T_TOK];

__device__ __forceinline__ uint32_t smem_u32(const void* p) {
    uint32_t a;
    asm("{ .reg .u64 t; cvta.to.shared.u64 t, %1; cvt.u32.u64 %0, t; }" : "=r"(a) : "l"(p));
    return a;
}
__device__ __forceinline__ void cp16(uint32_t dst, const void* src) {
    asm volatile("cp.async.cg.shared.global [%0], [%1], 16;" :: "r"(dst), "l"(src) : "memory");
}
__device__ __forceinline__ void cp_commit() {
    asm volatile("cp.async.commit_group;" ::: "memory");
}
template<int N>
__device__ __forceinline__ void cp_wait() {
    asm volatile("cp.async.wait_group %0;" :: "n"(N) : "memory");
}
__device__ __forceinline__ void ldsm_x4(uint32_t* r, uint32_t addr) {
    asm volatile("ldmatrix.sync.aligned.m8n8.x4.shared.b16 {%0,%1,%2,%3}, [%4];"
                 : "=r"(r[0]), "=r"(r[1]), "=r"(r[2]), "=r"(r[3]) : "r"(addr));
}
__device__ __forceinline__ void ldsm_x4_t(uint32_t* r, uint32_t addr) {
    asm volatile("ldmatrix.sync.aligned.m8n8.x4.trans.shared.b16 {%0,%1,%2,%3}, [%4];"
                 : "=r"(r[0]), "=r"(r[1]), "=r"(r[2]), "=r"(r[3]) : "r"(addr));
}
__device__ __forceinline__ void mma16816(float* c, const uint32_t* a, const uint32_t* b) {
    asm volatile(
        "mma.sync.aligned.m16n8k16.row.col.f32.f16.f16.f32 "
        "{%0,%1,%2,%3}, {%4,%5,%6,%7}, {%8,%9}, {%0,%1,%2,%3};"
        : "+f"(c[0]), "+f"(c[1]), "+f"(c[2]), "+f"(c[3])
        : "r"(a[0]), "r"(a[1]), "r"(a[2]), "r"(a[3]), "r"(b[0]), "r"(b[1]));
}

// ---------------- zero + router + convert ----------------
__global__ void zero_kernel(float* __restrict__ out) {
    size_t i = (size_t)blockIdx.x * blockDim.x + threadIdx.x;
    float4* o4 = (float4*)out;
    if (i < OUT_ELEMS / 4) o4[i] = make_float4(0.f, 0.f, 0.f, 0.f);
    if (i < E_NUM) g_cnt[i] = 0;
}

__global__ __launch_bounds__(256) void convert_kernel(
    const float4* __restrict__ src, uint2* __restrict__ dst, int n4) {
    int i = blockIdx.x * blockDim.x + threadIdx.x;
    if (i >= n4) return;
    float4 v = src[i];
    __half2 h0 = __floats2half2_rn(v.x, v.y);
    __half2 h1 = __floats2half2_rn(v.z, v.w);
    dst[i] = make_uint2(*(uint32_t*)&h0, *(uint32_t*)&h1);
}

__global__ __launch_bounds__(256) void router_kernel(
    const float* __restrict__ x, const float* __restrict__ gw,
    const float* __restrict__ gb, float* __restrict__ logits_out) {
    int warp = (blockIdx.x * blockDim.x + threadIdx.x) >> 5;
    int lane = threadIdx.x & 31;
    if (warp >= T_TOK) return;
    int t = warp;

    float acc[E_NUM];
#pragma unroll
    for (int e = 0; e < E_NUM; e++) acc[e] = 0.f;
    const float* xr = x + (size_t)t * D_DIM;
    for (int d = lane; d < D_DIM; d += 32) {
        float xv = xr[d];
        const float4* g4 = (const float4*)(gw + (size_t)d * E_NUM);
        float4 a = g4[0], b = g4[1];
        acc[0] += xv * a.x; acc[1] += xv * a.y; acc[2] += xv * a.z; acc[3] += xv * a.w;
        acc[4] += xv * b.x; acc[5] += xv * b.y; acc[6] += xv * b.z; acc[7] += xv * b.w;
    }
#pragma unroll
    for (int e = 0; e < E_NUM; e++)
#pragma unroll
        for (int off = 16; off; off >>= 1)
            acc[e] += __shfl_xor_sync(0xffffffffu, acc[e], off);

    if (lane == 0) {
        float l[E_NUM];
#pragma unroll
        for (int e = 0; e < E_NUM; e++) {
            l[e] = acc[e] + gb[e];
            logits_out[t * E_NUM + e] = l[e];
        }
        float m = l[0];
#pragma unroll
        for (int e = 1; e < E_NUM; e++) m = fmaxf(m, l[e]);
        float p[E_NUM], s = 0.f;
#pragma unroll
        for (int e = 0; e < E_NUM; e++) { p[e] = expf(l[e] - m); s += p[e]; }
#pragma unroll
        for (int e = 0; e < E_NUM; e++) p[e] = p[e] / s;
        int e0 = 0;
#pragma unroll
        for (int e = 1; e < E_NUM; e++) if (p[e] > p[e0]) e0 = e;
        int e1 = (e0 == 0) ? 1 : 0;
#pragma unroll
        for (int e = 0; e < E_NUM; e++)
            if (e != e0 && p[e] > p[e1]) e1 = e;
        float denom = p[e0] + p[e1];

        int pos0 = atomicAdd(&g_cnt[e0], 1);
        g_tok[e0 * T_TOK + pos0]  = t;
        g_slot[e0 * T_TOK + pos0] = 2 * t;
        g_wt[e0 * T_TOK + pos0]   = p[e0] / denom;
        int pos1 = atomicAdd(&g_cnt[e1], 1);
        g_tok[e1 * T_TOK + pos1]  = t;
        g_slot[e1 * T_TOK + pos1] = 2 * t + 1;
        g_wt[e1 * T_TOK + pos1]   = p[e1] / denom;
    }
}

// ---------------- grouped GEMM: 128x256 tile, warp 64x64, cp.async x3 ------
#define ASTR 40      // halfs per A smem row (32 + 8 pad) = 80B
#define BSTR 264     // halfs per B smem row (256 + 8 pad) = 528B
#define A_STAGE_B (128 * ASTR * 2)          // 10240
#define B_STAGE_B (32 * BSTR * 2)           // 16896
#define STAGE_B   (A_STAGE_B + B_STAGE_B)   // 27136
#define STAGES    3
#define SM_DYN    (STAGES * STAGE_B)        // 81408

template<int KTOT, int NTOT, bool FFN1>
__global__ __launch_bounds__(256, 1) void moe_gemm_kernel(
    const __half* __restrict__ Ain, const __half* __restrict__ W16,
    const float* __restrict__ Bias, float* __restrict__ OutP)
{
    const int NC = KTOT / 32;
    int e = blockIdx.z;
    int cnt = g_cnt[e];
    int rowbase = blockIdx.x * 128;
    if (rowbase >= cnt) return;
    int nbase = blockIdx.y * 256;
    int tid = threadIdx.x;
    int lane = tid & 31;
    int warp = tid >> 5;
    int wm = warp >> 2, wn = warp & 3;    // 2 x 4 warps, warp tile 64x64

    extern __shared__ char smdyn[];
    __shared__ int   dst_s[128];
    __shared__ float wt_s[128];
    __shared__ float bias_s[256];
    __shared__ int   src_s[128];

    if (tid < 128) {
        int r = rowbase + tid;
        int src = 0, dst = -1; float w = 0.f;
        if (r < cnt) {
            if (FFN1) { src = g_tok[e * T_TOK + r];  dst = g_slot[e * T_TOK + r]; }
            else      { src = g_slot[e * T_TOK + r]; dst = g_tok[e * T_TOK + r];
                        w = g_wt[e * T_TOK + r]; }
        }
        src_s[tid] = src; dst_s[tid] = dst; wt_s[tid] = w;
    }
    bias_s[tid] = Bias[(size_t)e * NTOT + nbase + tid];   // 256 threads = 256 entries
    __syncthreads();

    uint32_t smb = smem_u32(smdyn);

    // ---- loader assignments ----
    // A: 2 threads/row, each 2x16B (16 halfs). row = tid>>1, half-sel = tid&1
    int arow = tid >> 1;
    int acol = (tid & 1) * 16;                    // halfs
    const __half* aP = Ain + (size_t)src_s[arow] * KTOT + acol;
    uint32_t a_dst0 = (uint32_t)(arow * ASTR + acol) * 2;
    // B: 8 threads/row, each 4x16B (32 halfs). row = tid>>3, col0 = (tid&7)*32
    int brow = tid >> 3;
    int bcol = (tid & 7) * 32;                    // halfs
    const __half* bP = W16 + (size_t)e * KTOT * NTOT + (size_t)brow * NTOT + nbase + bcol;
    uint32_t b_dst0 = (uint32_t)(A_STAGE_B) + (uint32_t)(brow * BSTR + bcol) * 2;

    // ldmatrix base addresses
    int lr = lane & 15, lc = lane >> 4;
    uint32_t a_ld0 = (uint32_t)((wm * 64 + lr) * ASTR + lc * 8) * 2;
    uint32_t b_ld0 = (uint32_t)(A_STAGE_B) + (uint32_t)(lr * BSTR + wn * 64 + lc * 8) * 2;

    float acc[4][8][4];
#pragma unroll
    for (int i = 0; i < 4; i++)
#pragma unroll
        for (int j = 0; j < 8; j++)
#pragma unroll
            for (int k = 0; k < 4; k++) acc[i][j][k] = 0.f;

    // ---- cp.async stage loader ----
    auto issue_stage = [&](int c) {
        uint32_t sb = smb + (uint32_t)(c % STAGES) * STAGE_B;
        int k0 = c * 32;
        const __half* ap = aP + k0;
        cp16(sb + a_dst0,       ap);
        cp16(sb + a_dst0 + 32,  ap + 8);    // note: 16 halfs = 32 bytes apart? no:
        const __half* bp = bP + (size_t)k0 * NTOT;
#pragma unroll
        for (int j = 0; j < 4; j++)
            cp16(sb + b_dst0 + j * 16, bp + j * 8);
    };
    // fix A second cp: 8 halfs = 16 bytes; second 16B chunk starts at +8 halfs = +16B
    // (lambda above uses +32 by mistake? no — keep consistent: chunks are contiguous 16 halfs)
    // Each thread copies halfs [acol, acol+16): two cp16 at byte offsets +0 and +16.

#pragma unroll 1
    for (int s = 0; s < STAGES - 1; s++) {
        uint32_t sb = smb + (uint32_t)(s % STAGES) * STAGE_B;
        int k0 = s * 32;
        const __half* ap = aP + k0;
        cp16(sb + a_dst0,      ap);
        cp16(sb + a_dst0 + 16, ap + 8);
        const __half* bp = bP + (size_t)k0 * NTOT;
#pragma unroll
        for (int j = 0; j < 4; j++)
            cp16(sb + b_dst0 + j * 16, bp + j * 8);
        cp_commit();
    }

#pragma unroll 1
    for (int c = 0; c < NC; c++) {
        if (c + STAGES - 1 < NC) {
            int cs = c + STAGES - 1;
            uint32_t sb = smb + (uint32_t)(cs % STAGES) * STAGE_B;
            int k0 = cs * 32;
            const __half* ap = aP + k0;
            cp16(sb + a_dst0,      ap);
            cp16(sb + a_dst0 + 16, ap + 8);
            const __half* bp = bP + (size_t)k0 * NTOT;
#pragma unroll
            for (int j = 0; j < 4; j++)
                cp16(sb + b_dst0 + j * 16, bp + j * 8);
        }
        cp_commit();
        cp_wait<STAGES - 2>();
        __syncthreads();
        uint32_t sb = smb + (uint32_t)(c % STAGES) * STAGE_B;
#pragma unroll
        for (int ks = 0; ks < 2; ks++) {
            uint32_t afr[4][4], bfr[4][4];
#pragma unroll
            for (int mf = 0; mf < 4; mf++)
                ldsm_x4(afr[mf], sb + a_ld0 + (uint32_t)(mf * 16 * ASTR + ks * 16) * 2);
#pragma unroll
            for (int np = 0; np < 4; np++)
                ldsm_x4_t(bfr[np], sb + b_ld0 + (uint32_t)(ks * 16 * BSTR + np * 16) * 2);
#pragma unroll
            for (int mf = 0; mf < 4; mf++)
#pragma unroll
                for (int n8 = 0; n8 < 8; n8++)
                    mma16816(acc[mf][n8], afr[mf], &bfr[n8 >> 1][(n8 & 1) * 2]);
        }
        __syncthreads();
    }

    // ---- epilogue ----
    int crow = lane >> 2;
    int ccol = (lane & 3) * 2;
#pragma unroll
    for (int mf = 0; mf < 4; mf++) {
#pragma unroll
        for (int half_ = 0; half_ < 2; half_++) {
            int mloc = wm * 64 + mf * 16 + crow + half_ * 8;
            int dst = dst_s[mloc];
            if (dst < 0) continue;
            float wv = wt_s[mloc];
#pragma unroll
            for (int n8 = 0; n8 < 8; n8++) {
                int nloc = wn * 64 + n8 * 8 + ccol;
                float v0 = acc[mf][n8][half_ * 2 + 0] + bias_s[nloc];
                float v1 = acc[mf][n8][half_ * 2 + 1] + bias_s[nloc + 1];
                if (FFN1) {
                    v0 = 0.5f * v0 * (1.0f + erff(v0 * 0.70710678118654752f));
                    v1 = 0.5f * v1 * (1.0f + erff(v1 * 0.70710678118654752f));
                    __half2 h = __floats2half2_rn(v0, v1);
                    *(__half2*)(g_mid + (size_t)dst * NTOT + nbase + nloc) = h;
                } else {
                    float* o = OutP + (size_t)dst * NTOT + nbase + nloc;
                    atomicAdd(o,     wv * v0);
                    atomicAdd(o + 1, wv * v1);
                }
            }
        }
    }
}

// ---------------------------------------------------------------------------
extern "C" void kernel_launch(void* const* d_in, const int* in_sizes, int n_in,
                              void* d_out, int out_size) {
    const float* x      = (const float*)d_in[0];
    const float* gate_w = (const float*)d_in[1];
    const float* gate_b = (const float*)d_in[2];
    const float* w1     = (const float*)d_in[3];
    const float* b1     = (const float*)d_in[4];
    const float* w2     = (const float*)d_in[5];
    const float* b2     = (const float*)d_in[6];
    float* out    = (float*)d_out;
    float* logits = (float*)d_out + OUT_ELEMS;
    (void)in_sizes; (void)n_in; (void)out_size;

    __half *px, *pw1, *pw2, *pmid;
    cudaGetSymbolAddress((void**)&px,   g_x16);
    cudaGetSymbolAddress((void**)&pw1,  g_w1h);
    cudaGetSymbolAddress((void**)&pw2,  g_w2h);
    cudaGetSymbolAddress((void**)&pmid, g_mid);

    cudaFuncSetAttribute(moe_gemm_kernel<D_DIM, H_DIM, true>,
                         cudaFuncAttributeMaxDynamicSharedMemorySize, SM_DYN);
    cudaFuncSetAttribute(moe_gemm_kernel<H_DIM, D_DIM, false>,
                         cudaFuncAttributeMaxDynamicSharedMemorySize, SM_DYN);

    zero_kernel<<<(OUT_ELEMS / 4 + 255) / 256, 256>>>(out);
    router_kernel<<<(T_TOK * 32) / 256, 256>>>(x, gate_w, gate_b, logits);

    int nx = T_TOK * D_DIM / 4;
    convert_kernel<<<(nx + 255) / 256, 256>>>((const float4*)x, (uint2*)px, nx);
    int nw = E_NUM * D_DIM * H_DIM / 4;
    convert_kernel<<<(nw + 255) / 256, 256>>>((const float4*)w1, (uint2*)pw1, nw);
    convert_kernel<<<(nw + 255) / 256, 256>>>((const float4*)w2, (uint2*)pw2, nw);

    dim3 g1(T_TOK / 128, H_DIM / 256, E_NUM);   // (64, 16, 8)
    moe_gemm_kernel<D_DIM, H_DIM, true><<<g1, 256, SM_DYN>>>(px, pw1, b1, nullptr);

    dim3 g2(T_TOK / 128, D_DIM / 256, E_NUM);   // (64, 4, 8)
    moe_gemm_kernel<H_DIM, D_DIM, false><<<g2, 256, SM_DYN>>>(pmid, pw2, b2, out);
}

// round 6
// speedup vs baseline: 1.8310x; 1.8310x over previous
#include <cuda_runtime.h>
#include <cuda_fp16.h>
#include <math.h>
#include <stdint.h>

#define T_TOK 8192
#define D_DIM 1024
#define H_DIM 4096
#define E_NUM 8
#define OUT_ELEMS (T_TOK * D_DIM)

// ---------------- scratch ----------------
__device__ __half g_x16[(size_t)T_TOK * D_DIM];            // 16 MiB
__device__ __half g_w1h[(size_t)E_NUM * D_DIM * H_DIM];    // 64 MiB
__device__ __half g_w2h[(size_t)E_NUM * H_DIM * D_DIM];    // 64 MiB
__device__ __half g_mid[(size_t)2 * T_TOK * H_DIM];        // 128 MiB
__device__ int   g_cnt[E_NUM];
__device__ int   g_tok[E_NUM * T_TOK];
__device__ int   g_slot[E_NUM * T_TOK];
__device__ float g_wt[E_NUM * T_TOK];

__device__ __forceinline__ uint32_t smem_u32(const void* p) {
    uint32_t a;
    asm("{ .reg .u64 t; cvta.to.shared.u64 t, %1; cvt.u32.u64 %0, t; }" : "=r"(a) : "l"(p));
    return a;
}
__device__ __forceinline__ void cp16(uint32_t dst, const void* src) {
    asm volatile("cp.async.cg.shared.global [%0], [%1], 16;" :: "r"(dst), "l"(src) : "memory");
}
__device__ __forceinline__ void cp_commit() {
    asm volatile("cp.async.commit_group;" ::: "memory");
}
template<int N>
__device__ __forceinline__ void cp_wait() {
    asm volatile("cp.async.wait_group %0;" :: "n"(N) : "memory");
}
__device__ __forceinline__ void ldsm_x4(uint32_t* r, uint32_t addr) {
    asm volatile("ldmatrix.sync.aligned.m8n8.x4.shared.b16 {%0,%1,%2,%3}, [%4];"
                 : "=r"(r[0]), "=r"(r[1]), "=r"(r[2]), "=r"(r[3]) : "r"(addr));
}
__device__ __forceinline__ void ldsm_x4_t(uint32_t* r, uint32_t addr) {
    asm volatile("ldmatrix.sync.aligned.m8n8.x4.trans.shared.b16 {%0,%1,%2,%3}, [%4];"
                 : "=r"(r[0]), "=r"(r[1]), "=r"(r[2]), "=r"(r[3]) : "r"(addr));
}
__device__ __forceinline__ void mma16816(float* c, const uint32_t* a, const uint32_t* b) {
    asm volatile(
        "mma.sync.aligned.m16n8k16.row.col.f32.f16.f16.f32 "
        "{%0,%1,%2,%3}, {%4,%5,%6,%7}, {%8,%9}, {%0,%1,%2,%3};"
        : "+f"(c[0]), "+f"(c[1]), "+f"(c[2]), "+f"(c[3])
        : "r"(a[0]), "r"(a[1]), "r"(a[2]), "r"(a[3]), "r"(b[0]), "r"(b[1]));
}

// ---------------- zero + router + convert ----------------
__global__ void zero_kernel(float* __restrict__ out) {
    size_t i = (size_t)blockIdx.x * blockDim.x + threadIdx.x;
    float4* o4 = (float4*)out;
    if (i < OUT_ELEMS / 4) o4[i] = make_float4(0.f, 0.f, 0.f, 0.f);
    if (i < E_NUM) g_cnt[i] = 0;
}

__global__ __launch_bounds__(256) void convert_kernel(
    const float4* __restrict__ src, uint2* __restrict__ dst, int n4) {
    int i = blockIdx.x * blockDim.x + threadIdx.x;
    if (i >= n4) return;
    float4 v = src[i];
    __half2 h0 = __floats2half2_rn(v.x, v.y);
    __half2 h1 = __floats2half2_rn(v.z, v.w);
    dst[i] = make_uint2(*(uint32_t*)&h0, *(uint32_t*)&h1);
}

__global__ __launch_bounds__(256) void router_kernel(
    const float* __restrict__ x, const float* __restrict__ gw,
    const float* __restrict__ gb, float* __restrict__ logits_out) {
    int warp = (blockIdx.x * blockDim.x + threadIdx.x) >> 5;
    int lane = threadIdx.x & 31;
    if (warp >= T_TOK) return;
    int t = warp;

    float acc[E_NUM];
#pragma unroll
    for (int e = 0; e < E_NUM; e++) acc[e] = 0.f;
    const float* xr = x + (size_t)t * D_DIM;
    for (int d = lane; d < D_DIM; d += 32) {
        float xv = xr[d];
        const float4* g4 = (const float4*)(gw + (size_t)d * E_NUM);
        float4 a = g4[0], b = g4[1];
        acc[0] += xv * a.x; acc[1] += xv * a.y; acc[2] += xv * a.z; acc[3] += xv * a.w;
        acc[4] += xv * b.x; acc[5] += xv * b.y; acc[6] += xv * b.z; acc[7] += xv * b.w;
    }
#pragma unroll
    for (int e = 0; e < E_NUM; e++)
#pragma unroll
        for (int off = 16; off; off >>= 1)
            acc[e] += __shfl_xor_sync(0xffffffffu, acc[e], off);

    if (lane == 0) {
        float l[E_NUM];
#pragma unroll
        for (int e = 0; e < E_NUM; e++) {
            l[e] = acc[e] + gb[e];
            logits_out[t * E_NUM + e] = l[e];
        }
        float m = l[0];
#pragma unroll
        for (int e = 1; e < E_NUM; e++) m = fmaxf(m, l[e]);
        float p[E_NUM], s = 0.f;
#pragma unroll
        for (int e = 0; e < E_NUM; e++) { p[e] = expf(l[e] - m); s += p[e]; }
#pragma unroll
        for (int e = 0; e < E_NUM; e++) p[e] = p[e] / s;
        int e0 = 0;
#pragma unroll
        for (int e = 1; e < E_NUM; e++) if (p[e] > p[e0]) e0 = e;
        int e1 = (e0 == 0) ? 1 : 0;
#pragma unroll
        for (int e = 0; e < E_NUM; e++)
            if (e != e0 && p[e] > p[e1]) e1 = e;
        float denom = p[e0] + p[e1];

        int pos0 = atomicAdd(&g_cnt[e0], 1);
        g_tok[e0 * T_TOK + pos0]  = t;
        g_slot[e0 * T_TOK + pos0] = 2 * t;
        g_wt[e0 * T_TOK + pos0]   = p[e0] / denom;
        int pos1 = atomicAdd(&g_cnt[e1], 1);
        g_tok[e1 * T_TOK + pos1]  = t;
        g_slot[e1 * T_TOK + pos1] = 2 * t + 1;
        g_wt[e1 * T_TOK + pos1]   = p[e1] / denom;
    }
}

// ------- grouped GEMM: 128x128 tile, warp 64x32, cp.async 4-stage, 2 CTA/SM --
#define ASTR 40      // halfs per A smem row (32 + 8 pad) = 80B
#define BSTR 136     // halfs per B smem row (128 + 8 pad) = 272B
#define A_STAGE_B (128 * ASTR * 2)          // 10240
#define B_STAGE_B (32 * BSTR * 2)           // 8704
#define STAGE_B   (A_STAGE_B + B_STAGE_B)   // 18944
#define STAGES    4
#define SM_DYN    (STAGES * STAGE_B)        // 75776

template<int KTOT, int NTOT, bool FFN1>
__global__ __launch_bounds__(256, 2) void moe_gemm_kernel(
    const __half* __restrict__ Ain, const __half* __restrict__ W16,
    const float* __restrict__ Bias, float* __restrict__ OutP)
{
    const int NC = KTOT / 32;
    int e = blockIdx.z;
    int cnt = g_cnt[e];
    int rowbase = blockIdx.x * 128;
    if (rowbase >= cnt) return;
    int nbase = blockIdx.y * 128;
    int tid = threadIdx.x;
    int lane = tid & 31;
    int warp = tid >> 5;
    int wm = warp >> 2, wn = warp & 3;    // 2 x 4 warps, warp tile 64x32

    extern __shared__ char smdyn[];
    __shared__ int   dst_s[128];
    __shared__ float wt_s[128];
    __shared__ float bias_s[128];
    __shared__ int   src_s[128];

    if (tid < 128) {
        int r = rowbase + tid;
        int src = 0, dst = -1; float w = 0.f;
        if (r < cnt) {
            if (FFN1) { src = g_tok[e * T_TOK + r];  dst = g_slot[e * T_TOK + r]; }
            else      { src = g_slot[e * T_TOK + r]; dst = g_tok[e * T_TOK + r];
                        w = g_wt[e * T_TOK + r]; }
        }
        src_s[tid] = src; dst_s[tid] = dst; wt_s[tid] = w;
        bias_s[tid] = Bias[(size_t)e * NTOT + nbase + tid];
    }
    __syncthreads();

    uint32_t smb = smem_u32(smdyn);

    // A: 2 threads/row, each 2 cp16 (16 halfs). row = tid>>1
    int arow = tid >> 1;
    int acol = (tid & 1) * 16;
    const __half* aP = Ain + (size_t)src_s[arow] * KTOT + acol;
    uint32_t a_dst0 = (uint32_t)(arow * ASTR + acol) * 2;
    // B: 8 threads/row, each 2 cp16 (16 halfs). row = tid>>3, col = (tid&7)*16
    int brow = tid >> 3;
    int bcol = (tid & 7) * 16;
    const __half* bP = W16 + (size_t)e * KTOT * NTOT + (size_t)brow * NTOT + nbase + bcol;
    uint32_t b_dst0 = (uint32_t)(A_STAGE_B) + (uint32_t)(brow * BSTR + bcol) * 2;

    int lr = lane & 15, lc = lane >> 4;
    uint32_t a_ld0 = (uint32_t)((wm * 64 + lr) * ASTR + lc * 8) * 2;
    uint32_t b_ld0 = (uint32_t)(A_STAGE_B) + (uint32_t)(lr * BSTR + wn * 32 + lc * 8) * 2;

    float acc[4][4][4];
#pragma unroll
    for (int i = 0; i < 4; i++)
#pragma unroll
        for (int j = 0; j < 4; j++)
#pragma unroll
            for (int k = 0; k < 4; k++) acc[i][j][k] = 0.f;

#pragma unroll 1
    for (int s = 0; s < STAGES - 1; s++) {
        uint32_t sb = smb + (uint32_t)s * STAGE_B;
        int k0 = s * 32;
        const __half* ap = aP + k0;
        cp16(sb + a_dst0,      ap);
        cp16(sb + a_dst0 + 16, ap + 8);
        const __half* bp = bP + (size_t)k0 * NTOT;
        cp16(sb + b_dst0,      bp);
        cp16(sb + b_dst0 + 16, bp + 8);
        cp_commit();
    }

#pragma unroll 1
    for (int c = 0; c < NC; c++) {
        if (c + STAGES - 1 < NC) {
            int cs = c + STAGES - 1;
            uint32_t sb = smb + (uint32_t)(cs % STAGES) * STAGE_B;
            int k0 = cs * 32;
            const __half* ap = aP + k0;
            cp16(sb + a_dst0,      ap);
            cp16(sb + a_dst0 + 16, ap + 8);
            const __half* bp = bP + (size_t)k0 * NTOT;
            cp16(sb + b_dst0,      bp);
            cp16(sb + b_dst0 + 16, bp + 8);
        }
        cp_commit();
        cp_wait<STAGES - 2>();
        __syncthreads();
        uint32_t sb = smb + (uint32_t)(c % STAGES) * STAGE_B;
#pragma unroll
        for (int ks = 0; ks < 2; ks++) {
            uint32_t afr[4][4], bfr[2][4];
#pragma unroll
            for (int mf = 0; mf < 4; mf++)
                ldsm_x4(afr[mf], sb + a_ld0 + (uint32_t)(mf * 16 * ASTR + ks * 16) * 2);
#pragma unroll
            for (int np = 0; np < 2; np++)
                ldsm_x4_t(bfr[np], sb + b_ld0 + (uint32_t)(ks * 16 * BSTR + np * 16) * 2);
#pragma unroll
            for (int mf = 0; mf < 4; mf++)
#pragma unroll
                for (int nf = 0; nf < 4; nf++)
                    mma16816(acc[mf][nf], afr[mf], &bfr[nf >> 1][(nf & 1) * 2]);
        }
        __syncthreads();
    }

    // ---- epilogue ----
    int crow = lane >> 2;
    int ccol = (lane & 3) * 2;
#pragma unroll
    for (int mf = 0; mf < 4; mf++) {
#pragma unroll
        for (int half_ = 0; half_ < 2; half_++) {
            int mloc = wm * 64 + mf * 16 + crow + half_ * 8;
            int dst = dst_s[mloc];
            if (dst < 0) continue;
            float wv = wt_s[mloc];
#pragma unroll
            for (int nf = 0; nf < 4; nf++) {
                int nloc = wn * 32 + nf * 8 + ccol;
                float v0 = acc[mf][nf][half_ * 2 + 0] + bias_s[nloc];
                float v1 = acc[mf][nf][half_ * 2 + 1] + bias_s[nloc + 1];
                if (FFN1) {
                    v0 = 0.5f * v0 * (1.0f + erff(v0 * 0.70710678118654752f));
                    v1 = 0.5f * v1 * (1.0f + erff(v1 * 0.70710678118654752f));
                    __half2 h = __floats2half2_rn(v0, v1);
                    *(__half2*)(g_mid + (size_t)dst * NTOT + nbase + nloc) = h;
                } else {
                    float* o = OutP + (size_t)dst * NTOT + nbase + nloc;
                    atomicAdd(o,     wv * v0);
                    atomicAdd(o + 1, wv * v1);
                }
            }
        }
    }
}

// ---------------------------------------------------------------------------
extern "C" void kernel_launch(void* const* d_in, const int* in_sizes, int n_in,
                              void* d_out, int out_size) {
    const float* x      = (const float*)d_in[0];
    const float* gate_w = (const float*)d_in[1];
    const float* gate_b = (const float*)d_in[2];
    const float* w1     = (const float*)d_in[3];
    const float* b1     = (const float*)d_in[4];
    const float* w2     = (const float*)d_in[5];
    const float* b2     = (const float*)d_in[6];
    float* out    = (float*)d_out;
    float* logits = (float*)d_out + OUT_ELEMS;
    (void)in_sizes; (void)n_in; (void)out_size;

    __half *px, *pw1, *pw2, *pmid;
    cudaGetSymbolAddress((void**)&px,   g_x16);
    cudaGetSymbolAddress((void**)&pw1,  g_w1h);
    cudaGetSymbolAddress((void**)&pw2,  g_w2h);
    cudaGetSymbolAddress((void**)&pmid, g_mid);

    cudaFuncSetAttribute(moe_gemm_kernel<D_DIM, H_DIM, true>,
                         cudaFuncAttributeMaxDynamicSharedMemorySize, SM_DYN);
    cudaFuncSetAttribute(moe_gemm_kernel<H_DIM, D_DIM, false>,
                         cudaFuncAttributeMaxDynamicSharedMemorySize, SM_DYN);

    zero_kernel<<<(OUT_ELEMS / 4 + 255) / 256, 256>>>(out);
    router_kernel<<<(T_TOK * 32) / 256, 256>>>(x, gate_w, gate_b, logits);

    int nx = T_TOK * D_DIM / 4;
    convert_kernel<<<(nx + 255) / 256, 256>>>((const float4*)x, (uint2*)px, nx);
    int nw = E_NUM * D_DIM * H_DIM / 4;
    convert_kernel<<<(nw + 255) / 256, 256>>>((const float4*)w1, (uint2*)pw1, nw);
    convert_kernel<<<(nw + 255) / 256, 256>>>((const float4*)w2, (uint2*)pw2, nw);

    dim3 g1(T_TOK / 128, H_DIM / 128, E_NUM);   // (64, 32, 8)
    moe_gemm_kernel<D_DIM, H_DIM, true><<<g1, 256, SM_DYN>>>(px, pw1, b1, nullptr);

    dim3 g2(T_TOK / 128, D_DIM / 128, E_NUM);   // (64, 8, 8)
    moe_gemm_kernel<H_DIM, D_DIM, false><<<g2, 256, SM_DYN>>>(pmid, pw2, b2, out);
}

// round 7
// speedup vs baseline: 1.9907x; 1.0872x over previous
#include <cuda_runtime.h>
#include <cuda_fp16.h>
#include <math.h>
#include <stdint.h>

#define T_TOK 8192
#define D_DIM 1024
#define H_DIM 4096
#define E_NUM 8
#define OUT_ELEMS (T_TOK * D_DIM)

// ---------------- scratch ----------------
__device__ __half g_x16[(size_t)T_TOK * D_DIM];            // 16 MiB
__device__ __half g_w1h[(size_t)E_NUM * D_DIM * H_DIM];    // 64 MiB
__device__ __half g_w2h[(size_t)E_NUM * H_DIM * D_DIM];    // 64 MiB
__device__ __half g_mid[(size_t)2 * T_TOK * H_DIM];        // 128 MiB
__device__ float  g_out2[(size_t)2 * T_TOK * D_DIM];       // 64 MiB
__device__ int   g_cnt[E_NUM];
__device__ int   g_tok[E_NUM * T_TOK];
__device__ int   g_slot[E_NUM * T_TOK];
__device__ float g_wt[E_NUM * T_TOK];

__device__ __forceinline__ uint32_t smem_u32(const void* p) {
    uint32_t a;
    asm("{ .reg .u64 t; cvta.to.shared.u64 t, %1; cvt.u32.u64 %0, t; }" : "=r"(a) : "l"(p));
    return a;
}
__device__ __forceinline__ void cp16(uint32_t dst, const void* src) {
    asm volatile("cp.async.cg.shared.global [%0], [%1], 16;" :: "r"(dst), "l"(src) : "memory");
}
__device__ __forceinline__ void cp_commit() {
    asm volatile("cp.async.commit_group;" ::: "memory");
}
template<int N>
__device__ __forceinline__ void cp_wait() {
    asm volatile("cp.async.wait_group %0;" :: "n"(N) : "memory");
}
__device__ __forceinline__ void ldsm_x4(uint32_t* r, uint32_t addr) {
    asm volatile("ldmatrix.sync.aligned.m8n8.x4.shared.b16 {%0,%1,%2,%3}, [%4];"
                 : "=r"(r[0]), "=r"(r[1]), "=r"(r[2]), "=r"(r[3]) : "r"(addr));
}
__device__ __forceinline__ void ldsm_x4_t(uint32_t* r, uint32_t addr) {
    asm volatile("ldmatrix.sync.aligned.m8n8.x4.trans.shared.b16 {%0,%1,%2,%3}, [%4];"
                 : "=r"(r[0]), "=r"(r[1]), "=r"(r[2]), "=r"(r[3]) : "r"(addr));
}
__device__ __forceinline__ void mma16816(float* c, const uint32_t* a, const uint32_t* b) {
    asm volatile(
        "mma.sync.aligned.m16n8k16.row.col.f32.f16.f16.f32 "
        "{%0,%1,%2,%3}, {%4,%5,%6,%7}, {%8,%9}, {%0,%1,%2,%3};"
        : "+f"(c[0]), "+f"(c[1]), "+f"(c[2]), "+f"(c[3])
        : "r"(a[0]), "r"(a[1]), "r"(a[2]), "r"(a[3]), "r"(b[0]), "r"(b[1]));
}

// ---------------- small kernels ----------------
__global__ void zero_cnt_kernel() {
    if (threadIdx.x < E_NUM) g_cnt[threadIdx.x] = 0;
}

// 2x float4 -> uint4 (8 floats -> 8 halfs per thread)
__global__ __launch_bounds__(256) void convert_kernel(
    const float4* __restrict__ src, uint4* __restrict__ dst, int n8) {
    int i = blockIdx.x * blockDim.x + threadIdx.x;
    if (i >= n8) return;
    float4 v0 = src[2 * i], v1 = src[2 * i + 1];
    __half2 h0 = __floats2half2_rn(v0.x, v0.y);
    __half2 h1 = __floats2half2_rn(v0.z, v0.w);
    __half2 h2 = __floats2half2_rn(v1.x, v1.y);
    __half2 h3 = __floats2half2_rn(v1.z, v1.w);
    dst[i] = make_uint4(*(uint32_t*)&h0, *(uint32_t*)&h1,
                        *(uint32_t*)&h2, *(uint32_t*)&h3);
}

// out[t,d] = g_out2[2t,d] + g_out2[2t+1,d]
__global__ __launch_bounds__(256) void combine_kernel(float4* __restrict__ out) {
    int i = blockIdx.x * blockDim.x + threadIdx.x;           // float4 index
    if (i >= OUT_ELEMS / 4) return;
    int t = i / (D_DIM / 4);
    int r = i % (D_DIM / 4);
    const float4* a = (const float4*)g_out2 + (size_t)(2 * t) * (D_DIM / 4) + r;
    const float4* b = (const float4*)g_out2 + (size_t)(2 * t + 1) * (D_DIM / 4) + r;
    float4 va = *a, vb = *b;
    out[i] = make_float4(va.x + vb.x, va.y + vb.y, va.z + vb.z, va.w + vb.w);
}

__global__ __launch_bounds__(256) void router_kernel(
    const float* __restrict__ x, const float* __restrict__ gw,
    const float* __restrict__ gb, float* __restrict__ logits_out) {
    int warp = (blockIdx.x * blockDim.x + threadIdx.x) >> 5;
    int lane = threadIdx.x & 31;
    if (warp >= T_TOK) return;
    int t = warp;

    float acc[E_NUM];
#pragma unroll
    for (int e = 0; e < E_NUM; e++) acc[e] = 0.f;
    const float* xr = x + (size_t)t * D_DIM;
    for (int d = lane; d < D_DIM; d += 32) {
        float xv = xr[d];
        const float4* g4 = (const float4*)(gw + (size_t)d * E_NUM);
        float4 a = g4[0], b = g4[1];
        acc[0] += xv * a.x; acc[1] += xv * a.y; acc[2] += xv * a.z; acc[3] += xv * a.w;
        acc[4] += xv * b.x; acc[5] += xv * b.y; acc[6] += xv * b.z; acc[7] += xv * b.w;
    }
#pragma unroll
    for (int e = 0; e < E_NUM; e++)
#pragma unroll
        for (int off = 16; off; off >>= 1)
            acc[e] += __shfl_xor_sync(0xffffffffu, acc[e], off);

    if (lane == 0) {
        float l[E_NUM];
#pragma unroll
        for (int e = 0; e < E_NUM; e++) {
            l[e] = acc[e] + gb[e];
            logits_out[t * E_NUM + e] = l[e];
        }
        float m = l[0];
#pragma unroll
        for (int e = 1; e < E_NUM; e++) m = fmaxf(m, l[e]);
        float p[E_NUM], s = 0.f;
#pragma unroll
        for (int e = 0; e < E_NUM; e++) { p[e] = expf(l[e] - m); s += p[e]; }
#pragma unroll
        for (int e = 0; e < E_NUM; e++) p[e] = p[e] / s;
        int e0 = 0;
#pragma unroll
        for (int e = 1; e < E_NUM; e++) if (p[e] > p[e0]) e0 = e;
        int e1 = (e0 == 0) ? 1 : 0;
#pragma unroll
        for (int e = 0; e < E_NUM; e++)
            if (e != e0 && p[e] > p[e1]) e1 = e;
        float denom = p[e0] + p[e1];

        int pos0 = atomicAdd(&g_cnt[e0], 1);
        g_tok[e0 * T_TOK + pos0]  = t;
        g_slot[e0 * T_TOK + pos0] = 2 * t;
        g_wt[e0 * T_TOK + pos0]   = p[e0] / denom;
        int pos1 = atomicAdd(&g_cnt[e1], 1);
        g_tok[e1 * T_TOK + pos1]  = t;
        g_slot[e1 * T_TOK + pos1] = 2 * t + 1;
        g_wt[e1 * T_TOK + pos1]   = p[e1] / denom;
    }
}

// ------- grouped GEMM: 128x128 tile, warp 64x32, cp.async 4-stage, 2 CTA/SM --
#define ASTR 40      // halfs per A smem row (32 + 8 pad) = 80B
#define BSTR 136     // halfs per B smem row (128 + 8 pad) = 272B
#define A_STAGE_B (128 * ASTR * 2)          // 10240
#define B_STAGE_B (32 * BSTR * 2)           // 8704
#define STAGE_B   (A_STAGE_B + B_STAGE_B)   // 18944
#define STAGES    4
#define SM_DYN    (STAGES * STAGE_B)        // 75776

template<int KTOT, int NTOT, bool FFN1>
__global__ __launch_bounds__(256, 2) void moe_gemm_kernel(
    const __half* __restrict__ Ain, const __half* __restrict__ W16,
    const float* __restrict__ Bias)
{
    const int NC = KTOT / 32;
    int e = blockIdx.z;
    int cnt = g_cnt[e];
    int rowbase = blockIdx.x * 128;
    if (rowbase >= cnt) return;
    int nbase = blockIdx.y * 128;
    int tid = threadIdx.x;
    int lane = tid & 31;
    int warp = tid >> 5;
    int wm = warp >> 2, wn = warp & 3;    // 2 x 4 warps, warp tile 64x32

    extern __shared__ char smdyn[];
    __shared__ int   dst_s[128];
    __shared__ float wt_s[128];
    __shared__ float bias_s[128];
    __shared__ int   src_s[128];

    if (tid < 128) {
        int r = rowbase + tid;
        int src = 0, dst = -1; float w = 0.f;
        if (r < cnt) {
            if (FFN1) { src = g_tok[e * T_TOK + r];  dst = g_slot[e * T_TOK + r]; }
            else      { src = g_slot[e * T_TOK + r]; dst = g_slot[e * T_TOK + r];
                        w = g_wt[e * T_TOK + r]; }
        }
        src_s[tid] = src; dst_s[tid] = dst; wt_s[tid] = w;
        bias_s[tid] = Bias[(size_t)e * NTOT + nbase + tid];
    }
    __syncthreads();

    uint32_t smb = smem_u32(smdyn);

    // A: 2 threads/row, each 2 cp16 (16 halfs). row = tid>>1
    int arow = tid >> 1;
    int acol = (tid & 1) * 16;
    const __half* aP = Ain + (size_t)src_s[arow] * KTOT + acol;
    uint32_t a_dst0 = (uint32_t)(arow * ASTR + acol) * 2;
    // B: 8 threads/row, each 2 cp16 (16 halfs). row = tid>>3, col = (tid&7)*16
    int brow = tid >> 3;
    int bcol = (tid & 7) * 16;
    const __half* bP = W16 + (size_t)e * KTOT * NTOT + (size_t)brow * NTOT + nbase + bcol;
    uint32_t b_dst0 = (uint32_t)(A_STAGE_B) + (uint32_t)(brow * BSTR + bcol) * 2;

    int lr = lane & 15, lc = lane >> 4;
    uint32_t a_ld0 = (uint32_t)((wm * 64 + lr) * ASTR + lc * 8) * 2;
    uint32_t b_ld0 = (uint32_t)(A_STAGE_B) + (uint32_t)(lr * BSTR + wn * 32 + lc * 8) * 2;

    float acc[4][4][4];
#pragma unroll
    for (int i = 0; i < 4; i++)
#pragma unroll
        for (int j = 0; j < 4; j++)
#pragma unroll
            for (int k = 0; k < 4; k++) acc[i][j][k] = 0.f;

#pragma unroll 1
    for (int s = 0; s < STAGES - 1; s++) {
        uint32_t sb = smb + (uint32_t)s * STAGE_B;
        int k0 = s * 32;
        const __half* ap = aP + k0;
        cp16(sb + a_dst0,      ap);
        cp16(sb + a_dst0 + 16, ap + 8);
        const __half* bp = bP + (size_t)k0 * NTOT;
        cp16(sb + b_dst0,      bp);
        cp16(sb + b_dst0 + 16, bp + 8);
        cp_commit();
    }

#pragma unroll 1
    for (int c = 0; c < NC; c++) {
        cp_wait<STAGES - 2>();
        __syncthreads();
        // issue stage c+STAGES-1 into the buffer freed by compute of (c-1);
        // all threads passed the barrier, so all finished that compute.
        if (c + STAGES - 1 < NC) {
            int cs = c + STAGES - 1;
            uint32_t sbw = smb + (uint32_t)(cs % STAGES) * STAGE_B;
            int k0 = cs * 32;
            const __half* ap = aP + k0;
            cp16(sbw + a_dst0,      ap);
            cp16(sbw + a_dst0 + 16, ap + 8);
            const __half* bp = bP + (size_t)k0 * NTOT;
            cp16(sbw + b_dst0,      bp);
            cp16(sbw + b_dst0 + 16, bp + 8);
        }
        cp_commit();
        uint32_t sb = smb + (uint32_t)(c % STAGES) * STAGE_B;
#pragma unroll
        for (int ks = 0; ks < 2; ks++) {
            uint32_t afr[4][4], bfr[2][4];
#pragma unroll
            for (int mf = 0; mf < 4; mf++)
                ldsm_x4(afr[mf], sb + a_ld0 + (uint32_t)(mf * 16 * ASTR + ks * 16) * 2);
#pragma unroll
            for (int np = 0; np < 2; np++)
                ldsm_x4_t(bfr[np], sb + b_ld0 + (uint32_t)(ks * 16 * BSTR + np * 16) * 2);
#pragma unroll
            for (int mf = 0; mf < 4; mf++)
#pragma unroll
                for (int nf = 0; nf < 4; nf++)
                    mma16816(acc[mf][nf], afr[mf], &bfr[nf >> 1][(nf & 1) * 2]);
        }
    }

    // ---- epilogue ----
    int crow = lane >> 2;
    int ccol = (lane & 3) * 2;
#pragma unroll
    for (int mf = 0; mf < 4; mf++) {
#pragma unroll
        for (int half_ = 0; half_ < 2; half_++) {
            int mloc = wm * 64 + mf * 16 + crow + half_ * 8;
            int dst = dst_s[mloc];
            if (dst < 0) continue;
            float wv = wt_s[mloc];
#pragma unroll
            for (int nf = 0; nf < 4; nf++) {
                int nloc = wn * 32 + nf * 8 + ccol;
                float v0 = acc[mf][nf][half_ * 2 + 0] + bias_s[nloc];
                float v1 = acc[mf][nf][half_ * 2 + 1] + bias_s[nloc + 1];
                if (FFN1) {
                    v0 = 0.5f * v0 * (1.0f + erff(v0 * 0.70710678118654752f));
                    v1 = 0.5f * v1 * (1.0f + erff(v1 * 0.70710678118654752f));
                    __half2 h = __floats2half2_rn(v0, v1);
                    *(__half2*)(g_mid + (size_t)dst * NTOT + nbase + nloc) = h;
                } else {
                    // non-atomic: each slot row written exactly once
                    float2 o = make_float2(wv * v0, wv * v1);
                    *(float2*)(g_out2 + (size_t)dst * NTOT + nbase + nloc) = o;
                }
            }
        }
    }
}

// ---------------------------------------------------------------------------
extern "C" void kernel_launch(void* const* d_in, const int* in_sizes, int n_in,
                              void* d_out, int out_size) {
    const float* x      = (const float*)d_in[0];
    const float* gate_w = (const float*)d_in[1];
    const float* gate_b = (const float*)d_in[2];
    const float* w1     = (const float*)d_in[3];
    const float* b1     = (const float*)d_in[4];
    const float* w2     = (const float*)d_in[5];
    const float* b2     = (const float*)d_in[6];
    float* out    = (float*)d_out;
    float* logits = (float*)d_out + OUT_ELEMS;
    (void)in_sizes; (void)n_in; (void)out_size;

    __half *px, *pw1, *pw2, *pmid;
    cudaGetSymbolAddress((void**)&px,   g_x16);
    cudaGetSymbolAddress((void**)&pw1,  g_w1h);
    cudaGetSymbolAddress((void**)&pw2,  g_w2h);
    cudaGetSymbolAddress((void**)&pmid, g_mid);

    cudaFuncSetAttribute(moe_gemm_kernel<D_DIM, H_DIM, true>,
                         cudaFuncAttributeMaxDynamicSharedMemorySize, SM_DYN);
    cudaFuncSetAttribute(moe_gemm_kernel<H_DIM, D_DIM, false>,
                         cudaFuncAttributeMaxDynamicSharedMemorySize, SM_DYN);

    zero_cnt_kernel<<<1, 32>>>();
    router_kernel<<<(T_TOK * 32) / 256, 256>>>(x, gate_w, gate_b, logits);

    int nx8 = T_TOK * D_DIM / 8;
    convert_kernel<<<(nx8 + 255) / 256, 256>>>((const float4*)x, (uint4*)px, nx8);
    int nw8 = E_NUM * D_DIM * H_DIM / 8;
    convert_kernel<<<(nw8 + 255) / 256, 256>>>((const float4*)w1, (uint4*)pw1, nw8);
    convert_kernel<<<(nw8 + 255) / 256, 256>>>((const float4*)w2, (uint4*)pw2, nw8);

    dim3 g1(T_TOK / 128, H_DIM / 128, E_NUM);   // (64, 32, 8)
    moe_gemm_kernel<D_DIM, H_DIM, true><<<g1, 256, SM_DYN>>>(px, pw1, b1);

    dim3 g2(T_TOK / 128, D_DIM / 128, E_NUM);   // (64, 8, 8)
    moe_gemm_kernel<H_DIM, D_DIM, false><<<g2, 256, SM_DYN>>>(pmid, pw2, b2);

    combine_kernel<<<(OUT_ELEMS / 4 + 255) / 256, 256>>>((float4*)out);
}